// round 4
// baseline (speedup 1.0000x reference)
#include <cuda_runtime.h>
#include <cstdint>

// TopologyTracker: 64x64 histogram of (prev, curr) transitions over 16.7M events.
// Output layout (float32): [0..4095] = transitions + counts, [4096] = total + N.
//
// R4 strategy: the smem atomic ALU floor (2 lanes/cyc/SM) capped the atomic
// version at ~28us. Eliminate hot-loop atomics entirely:
//   - per-WARP private u16 histogram (8KB/warp, 64KB/CTA dynamic smem)
//   - __match_any_sync dedups same-bin lanes; leader does plain u16 RMW
// Epilogue: CTA-level reduce of 8 warp hists -> one float atomic per bin.

#define NUM_TILES 64
#define NUM_BINS  (NUM_TILES * NUM_TILES)   // 4096
#define THREADS   256
#define WARPS     (THREADS / 32)            // 8
#define SMEM_BYTES (WARPS * NUM_BINS * 2)   // 64KB u16

// ---------------------------------------------------------------------------
// Kernel 1: seed output with the incoming transitions matrix + updated total.
// ---------------------------------------------------------------------------
__global__ void tt_init_out(const float* __restrict__ trans_in,
                            const float* __restrict__ total_in,
                            float* __restrict__ out,
                            int out_size,
                            float n_events)
{
    int i = blockIdx.x * blockDim.x + threadIdx.x;
    if (i < NUM_BINS && i < out_size) {
        out[i] = trans_in[i];
    }
    if (i == NUM_BINS && i < out_size) {
        out[NUM_BINS] = total_in[0] + n_events;
    }
}

// One warp-wide dedup-and-accumulate round. b < NUM_BINS means valid;
// invalid lanes carry unique sentinel bins (NUM_BINS + lane) so they never
// alias a valid bin or each other.
__device__ __forceinline__ void hist_round(unsigned short* __restrict__ hw,
                                           int b, int lane)
{
    unsigned m = __match_any_sync(0xffffffffu, b);
    int leader = __ffs(m) - 1;
    if (lane == leader && b < NUM_BINS) {
        hw[b] = (unsigned short)(hw[b] + (unsigned short)__popc(m));
    }
}

// ---------------------------------------------------------------------------
// Kernel 2: histogram accumulation, atomic-free hot loop.
// ---------------------------------------------------------------------------
__global__ void __launch_bounds__(THREADS, 3)
tt_hist(const int* __restrict__ prev,
        const int* __restrict__ curr,
        float* __restrict__ out,
        int n)
{
    extern __shared__ unsigned short h[];   // [WARPS][NUM_BINS] u16

    // Zero all warp histograms (64KB) with 16B stores.
    {
        uint4* h4 = reinterpret_cast<uint4*>(h);
        const uint4 z = make_uint4(0, 0, 0, 0);
        #pragma unroll
        for (int i = threadIdx.x; i < SMEM_BYTES / 16; i += THREADS) {
            h4[i] = z;
        }
    }
    __syncthreads();

    const int lane   = threadIdx.x & 31;
    const int warpId = blockIdx.x * WARPS + (threadIdx.x >> 5);
    const int nWarps = gridDim.x * WARPS;
    unsigned short* __restrict__ hw = h + (size_t)(threadIdx.x >> 5) * NUM_BINS;

    const int4* __restrict__ p4 = reinterpret_cast<const int4*>(prev);
    const int4* __restrict__ c4 = reinterpret_cast<const int4*>(curr);

    const int n8 = n >> 3;     // int4-pair groups (8 events each)
    const int SENT = NUM_BINS + lane;  // unique per-lane sentinel bin

    // Warp-uniform outer loop: every lane executes the same trip count, so
    // __match_any_sync always runs with a full converged warp.
    for (int base = warpId * 32; base < n8; base += nWarps * 32) {
        int i = base + lane;
        bool valid = (i < n8);
        int i_ld = valid ? i : (n8 - 1);   // clamp: safe dummy load

        int4 pa = __ldcs(&p4[2 * i_ld]);
        int4 pb = __ldcs(&p4[2 * i_ld + 1]);
        int4 ca = __ldcs(&c4[2 * i_ld]);
        int4 cb = __ldcs(&c4[2 * i_ld + 1]);

        int b0 = valid ? ((pa.x << 6) + ca.x) : SENT;
        int b1 = valid ? ((pa.y << 6) + ca.y) : SENT;
        int b2 = valid ? ((pa.z << 6) + ca.z) : SENT;
        int b3 = valid ? ((pa.w << 6) + ca.w) : SENT;
        int b4 = valid ? ((pb.x << 6) + cb.x) : SENT;
        int b5 = valid ? ((pb.y << 6) + cb.y) : SENT;
        int b6 = valid ? ((pb.z << 6) + cb.z) : SENT;
        int b7 = valid ? ((pb.w << 6) + cb.w) : SENT;

        hist_round(hw, b0, lane);
        hist_round(hw, b1, lane);
        hist_round(hw, b2, lane);
        hist_round(hw, b3, lane);
        hist_round(hw, b4, lane);
        hist_round(hw, b5, lane);
        hist_round(hw, b6, lane);
        hist_round(hw, b7, lane);
    }

    // Scalar tail (n % 8 events), handled by warp 0 of block 0 only.
    if (blockIdx.x == 0 && (threadIdx.x >> 5) == 0) {
        int tail_start = n8 << 3;
        int rem = n - tail_start;
        if (rem > 0) {
            int i = tail_start + lane;
            int b = (lane < rem) ? ((prev[i] << 6) + curr[i]) : SENT;
            hist_round(hw, b, lane);
        }
    }

    __syncthreads();

    // CTA reduce: sum 8 warp hists per bin, one float atomic per bin.
    for (int bin = threadIdx.x; bin < NUM_BINS; bin += THREADS) {
        int s = 0;
        #pragma unroll
        for (int w = 0; w < WARPS; w++) {
            s += h[w * NUM_BINS + bin];
        }
        if (s != 0) {
            atomicAdd(&out[bin], (float)s);
        }
    }
}

// ---------------------------------------------------------------------------
// Launcher
// ---------------------------------------------------------------------------
extern "C" void kernel_launch(void* const* d_in, const int* in_sizes, int n_in,
                              void* d_out, int out_size)
{
    const int*   prev     = (const int*)  d_in[0];
    const int*   curr     = (const int*)  d_in[1];
    const float* trans_in = (const float*)d_in[2];
    const float* total_in = (const float*)d_in[3];
    float*       out      = (float*)d_out;

    const int n = in_sizes[0];

    // Allow 64KB dynamic smem (idempotent; host-side, no allocation).
    cudaFuncSetAttribute(tt_hist, cudaFuncAttributeMaxDynamicSharedMemorySize,
                         SMEM_BYTES);

    // Seed output first (flush atomics in tt_hist depend on it).
    tt_init_out<<<(NUM_BINS + 1 + 255) / 256, 256>>>(trans_in, total_in, out,
                                                     out_size, (float)n);

    // Histogram accumulation: 3 CTAs/SM * 148 SMs.
    tt_hist<<<444, THREADS, SMEM_BYTES>>>(prev, curr, out, n);
}

// round 5
// speedup vs baseline: 1.2054x; 1.2054x over previous
#include <cuda_runtime.h>
#include <cstdint>

// TopologyTracker: 64x64 histogram of (prev, curr) transitions over 16.7M events.
// Output layout (float32): [0..4095] = transitions + counts, [4096] = total + N.
//
// R5: smem-ATOMS floor (~28us) is the binding unit. Offload 2/8 of the
// increments to L2 REDG into per-CTA-PRIVATE scratch (R3 failed because
// scratch was shared across CTAs -> per-address LTS serialization; private
// regions remove that). Smem histogram flush also lands in the private
// scratch. Finalize reduces all regions + trans_in -> out and re-zeroes
// scratch (graph-replay-safe by induction; module load zero-init covers
// the first call).

#define NUM_TILES 64
#define NUM_BINS  (NUM_TILES * NUM_TILES)   // 4096
#define THREADS   512
#define GRID      296                        // 2 CTAs/SM * 148 SMs
#define CREP      2                          // per-CTA scratch replicas
#define NREGION   (GRID * CREP)              // 592 scratch regions

// Per-CTA-private scratch. Zeroed at module load; finalize re-zeroes.
__device__ int g_scratch[NREGION][NUM_BINS];

// ---------------------------------------------------------------------------
// Kernel 1: histogram accumulation.
// ---------------------------------------------------------------------------
__global__ void __launch_bounds__(THREADS, 2)
tt_hist(const int* __restrict__ prev,
        const int* __restrict__ curr,
        int n)
{
    __shared__ int h[NUM_BINS];

    #pragma unroll
    for (int i = threadIdx.x; i < NUM_BINS; i += THREADS) {
        h[i] = 0;
    }
    __syncthreads();

    // Private scratch region for this CTA: replica chosen by warp parity
    // to halve intra-CTA same-address concurrency at the LTS.
    const int warp = threadIdx.x >> 5;
    int* __restrict__ gs = g_scratch[blockIdx.x * CREP + (warp & 1)];

    const int tid    = blockIdx.x * THREADS + threadIdx.x;
    const int stride = gridDim.x * THREADS;

    const int4* __restrict__ p4 = reinterpret_cast<const int4*>(prev);
    const int4* __restrict__ c4 = reinterpret_cast<const int4*>(curr);

    // 8 events per iteration: 4 front-batched 16B streaming loads.
    const int n8 = n >> 3;
    for (int i = tid; i < n8; i += stride) {
        int4 pa = __ldcs(&p4[2 * i]);
        int4 pb = __ldcs(&p4[2 * i + 1]);
        int4 ca = __ldcs(&c4[2 * i]);
        int4 cb = __ldcs(&c4[2 * i + 1]);

        // 6 increments on the smem atomic pipe...
        atomicAdd(&h[(pa.x << 6) + ca.x], 1);
        atomicAdd(&h[(pa.y << 6) + ca.y], 1);
        atomicAdd(&h[(pa.z << 6) + ca.z], 1);
        atomicAdd(&h[(pa.w << 6) + ca.w], 1);
        atomicAdd(&h[(pb.x << 6) + cb.x], 1);
        atomicAdd(&h[(pb.y << 6) + cb.y], 1);
        // ...2 on the L2 atomic pipe, private region (RED.E.ADD, no return).
        atomicAdd(&gs[(pb.z << 6) + cb.z], 1);
        atomicAdd(&gs[(pb.w << 6) + cb.w], 1);
    }

    // Scalar tail (N divisible by 8 in practice; kept for safety).
    for (int i = (n8 << 3) + tid; i < n; i += stride) {
        atomicAdd(&h[(prev[i] << 6) + curr[i]], 1);
    }

    __syncthreads();

    // Flush smem histogram into this CTA's private scratch.
    #pragma unroll
    for (int i = threadIdx.x; i < NUM_BINS; i += THREADS) {
        int v = h[i];
        if (v != 0) {
            atomicAdd(&gs[i], v);
        }
    }
}

// ---------------------------------------------------------------------------
// Kernel 2: finalize. out = trans_in + sum over all scratch regions;
// re-zero scratch; write updated total. All values integer < 2^24 -> exact.
// Layout: each warp sweeps 32 consecutive bins across regions (coalesced).
// ---------------------------------------------------------------------------
__global__ void __launch_bounds__(512)
tt_finalize(const float* __restrict__ trans_in,
            const float* __restrict__ total_in,
            float* __restrict__ out,
            int out_size,
            float n_events)
{
    int bin = blockIdx.x * blockDim.x + threadIdx.x;
    if (bin < NUM_BINS && bin < out_size) {
        int s = 0;
        for (int r = 0; r < NREGION; r++) {
            s += g_scratch[r][bin];
            g_scratch[r][bin] = 0;
        }
        out[bin] = trans_in[bin] + (float)s;
    }
    if (bin == NUM_BINS && bin < out_size) {
        out[NUM_BINS] = total_in[0] + n_events;
    }
}

// ---------------------------------------------------------------------------
// Launcher
// ---------------------------------------------------------------------------
extern "C" void kernel_launch(void* const* d_in, const int* in_sizes, int n_in,
                              void* d_out, int out_size)
{
    const int*   prev     = (const int*)  d_in[0];
    const int*   curr     = (const int*)  d_in[1];
    const float* trans_in = (const float*)d_in[2];
    const float* total_in = (const float*)d_in[3];
    float*       out      = (float*)d_out;

    const int n = in_sizes[0];

    tt_hist<<<GRID, THREADS>>>(prev, curr, n);

    tt_finalize<<<(NUM_BINS + 1 + 511) / 512, 512>>>(trans_in, total_in, out,
                                                     out_size, (float)n);
}

// round 6
// speedup vs baseline: 1.3333x; 1.1061x over previous
#include <cuda_runtime.h>
#include <cstdint>

// TopologyTracker: 64x64 histogram of (prev, curr) transitions over 16.7M events.
// Output layout (float32): [0..4095] = transitions + counts, [4096] = total + N.
//
// R6: 6/8 of increments -> per-CTA smem ATOMS (measured floor ~28us alone);
// 2/8 -> RED.E.ADD into per-CTA-PRIVATE L2 scratch (2 replicas/CTA, chosen by
// warp parity; ~1.75 ops/address -> no LTS same-address serialization).
// Epilogue is fully CTA-local: read own scratch, re-zero it (induction ->
// graph-replay safe), add to smem counts, one float atomic per bin to out.
// Init kernel seeds out with trans_in and writes the total first.

#define NUM_TILES 64
#define NUM_BINS  (NUM_TILES * NUM_TILES)   // 4096
#define THREADS   512
#define GRID      296                        // 2 CTAs/SM * 148 SMs
#define CREP      2                          // per-CTA scratch replicas
#define NREGION   (GRID * CREP)              // 592 regions, ~9.7MB (L2-resident)

// Zero-initialized at module load; each CTA re-zeroes its own regions every
// call, so they are always 0 on entry.
__device__ int g_scratch[NREGION][NUM_BINS];

// ---------------------------------------------------------------------------
// Kernel 1: seed output with incoming transitions matrix + updated total.
// ---------------------------------------------------------------------------
__global__ void tt_init_out(const float* __restrict__ trans_in,
                            const float* __restrict__ total_in,
                            float* __restrict__ out,
                            int out_size,
                            float n_events)
{
    int i = blockIdx.x * blockDim.x + threadIdx.x;
    if (i < NUM_BINS && i < out_size) {
        out[i] = trans_in[i];
    }
    if (i == NUM_BINS && i < out_size) {
        out[NUM_BINS] = total_in[0] + n_events;
    }
}

// ---------------------------------------------------------------------------
// Kernel 2: histogram accumulation + fully CTA-local epilogue.
// ---------------------------------------------------------------------------
__global__ void __launch_bounds__(THREADS, 2)
tt_hist(const int* __restrict__ prev,
        const int* __restrict__ curr,
        float* __restrict__ out,
        int n)
{
    __shared__ int h[NUM_BINS];

    #pragma unroll
    for (int i = threadIdx.x; i < NUM_BINS; i += THREADS) {
        h[i] = 0;
    }
    __syncthreads();

    // Private scratch replica: warp parity halves intra-CTA concurrency.
    const int warp = threadIdx.x >> 5;
    int* __restrict__ gs = g_scratch[blockIdx.x * CREP + (warp & 1)];

    const int tid    = blockIdx.x * THREADS + threadIdx.x;
    const int stride = gridDim.x * THREADS;

    const int4* __restrict__ p4 = reinterpret_cast<const int4*>(prev);
    const int4* __restrict__ c4 = reinterpret_cast<const int4*>(curr);

    // 8 events per iteration: 4 front-batched 16B streaming loads.
    const int n8 = n >> 3;
    for (int i = tid; i < n8; i += stride) {
        int4 pa = __ldcs(&p4[2 * i]);
        int4 pb = __ldcs(&p4[2 * i + 1]);
        int4 ca = __ldcs(&c4[2 * i]);
        int4 cb = __ldcs(&c4[2 * i + 1]);

        // 6 increments on the smem atomic pipe...
        atomicAdd(&h[(pa.x << 6) + ca.x], 1);
        atomicAdd(&h[(pa.y << 6) + ca.y], 1);
        atomicAdd(&h[(pa.z << 6) + ca.z], 1);
        atomicAdd(&h[(pa.w << 6) + ca.w], 1);
        atomicAdd(&h[(pb.x << 6) + cb.x], 1);
        atomicAdd(&h[(pb.y << 6) + cb.y], 1);
        // ...2 on the L2 atomic pipe into CTA-private scratch (RED, no return).
        atomicAdd(&gs[(pb.z << 6) + cb.z], 1);
        atomicAdd(&gs[(pb.w << 6) + cb.w], 1);
    }

    // Scalar tail (N divisible by 8 in practice; kept for safety).
    for (int i = (n8 << 3) + tid; i < n; i += stride) {
        atomicAdd(&h[(prev[i] << 6) + curr[i]], 1);
    }

    __syncthreads();

    // Epilogue: fold this CTA's two private scratch regions into the smem
    // counts, re-zero them, and flush to out with one float atomic per bin.
    int* __restrict__ r0 = g_scratch[blockIdx.x * CREP + 0];
    int* __restrict__ r1 = g_scratch[blockIdx.x * CREP + 1];
    #pragma unroll
    for (int i = threadIdx.x; i < NUM_BINS; i += THREADS) {
        int v = h[i] + r0[i] + r1[i];
        r0[i] = 0;
        r1[i] = 0;
        if (v != 0) {
            atomicAdd(&out[i], (float)v);
        }
    }
}

// ---------------------------------------------------------------------------
// Launcher
// ---------------------------------------------------------------------------
extern "C" void kernel_launch(void* const* d_in, const int* in_sizes, int n_in,
                              void* d_out, int out_size)
{
    const int*   prev     = (const int*)  d_in[0];
    const int*   curr     = (const int*)  d_in[1];
    const float* trans_in = (const float*)d_in[2];
    const float* total_in = (const float*)d_in[3];
    float*       out      = (float*)d_out;

    const int n = in_sizes[0];

    // Seed output first; hist epilogue atomics accumulate onto it.
    tt_init_out<<<(NUM_BINS + 1 + 255) / 256, 256>>>(trans_in, total_in, out,
                                                     out_size, (float)n);

    tt_hist<<<GRID, THREADS>>>(prev, curr, out, n);
}

// round 7
// speedup vs baseline: 3.9065x; 2.9299x over previous
#include <cuda_runtime.h>
#include <cstdint>

// TopologyTracker: 64x64 histogram of (prev, curr) transitions over 16.7M events.
// Output layout (float32): [0..4095] = transitions + counts, [4096] = total + N.
//
// R7: hot loop = LDG + smem ATOMS only (all offload paths measured and
// falsified). The smem atomic unit floor (2 lanes/cyc/SM) binds at ~28us;
// minimize everything around it: 1 CTA/SM (halves flush atomics + zeroing),
// 16 events per thread-iteration for deep MLP.

#define NUM_TILES 64
#define NUM_BINS  (NUM_TILES * NUM_TILES)   // 4096
#define THREADS   1024
#define GRID      148                        // 1 CTA/SM

// ---------------------------------------------------------------------------
// Kernel 1: seed output with the incoming transitions matrix + updated total.
// ---------------------------------------------------------------------------
__global__ void tt_init_out(const float* __restrict__ trans_in,
                            const float* __restrict__ total_in,
                            float* __restrict__ out,
                            int out_size,
                            float n_events)
{
    int i = blockIdx.x * blockDim.x + threadIdx.x;
    if (i < NUM_BINS && i < out_size) {
        out[i] = trans_in[i];
    }
    if (i == NUM_BINS && i < out_size) {
        out[NUM_BINS] = total_in[0] + n_events;
    }
}

// ---------------------------------------------------------------------------
// Kernel 2: per-CTA shared histogram; 16 events/iter; single flush per bin.
// ---------------------------------------------------------------------------
__global__ void __launch_bounds__(THREADS, 1)
tt_hist(const int* __restrict__ prev,
        const int* __restrict__ curr,
        float* __restrict__ out,
        int n)
{
    __shared__ int h[NUM_BINS];

    #pragma unroll
    for (int i = threadIdx.x; i < NUM_BINS; i += THREADS) {
        h[i] = 0;
    }
    __syncthreads();

    const int tid    = blockIdx.x * THREADS + threadIdx.x;
    const int stride = gridDim.x * THREADS;

    const int4* __restrict__ p4 = reinterpret_cast<const int4*>(prev);
    const int4* __restrict__ c4 = reinterpret_cast<const int4*>(curr);

    // 16 events per iteration: 8 front-batched 16B loads (4 per stream).
    const int n16 = n >> 4;
    for (int i = tid; i < n16; i += stride) {
        int4 pa = p4[4 * i];
        int4 pb = p4[4 * i + 1];
        int4 pc = p4[4 * i + 2];
        int4 pd = p4[4 * i + 3];
        int4 ca = c4[4 * i];
        int4 cb = c4[4 * i + 1];
        int4 cc = c4[4 * i + 2];
        int4 cd = c4[4 * i + 3];

        atomicAdd(&h[(pa.x << 6) + ca.x], 1);
        atomicAdd(&h[(pa.y << 6) + ca.y], 1);
        atomicAdd(&h[(pa.z << 6) + ca.z], 1);
        atomicAdd(&h[(pa.w << 6) + ca.w], 1);
        atomicAdd(&h[(pb.x << 6) + cb.x], 1);
        atomicAdd(&h[(pb.y << 6) + cb.y], 1);
        atomicAdd(&h[(pb.z << 6) + cb.z], 1);
        atomicAdd(&h[(pb.w << 6) + cb.w], 1);
        atomicAdd(&h[(pc.x << 6) + cc.x], 1);
        atomicAdd(&h[(pc.y << 6) + cc.y], 1);
        atomicAdd(&h[(pc.z << 6) + cc.z], 1);
        atomicAdd(&h[(pc.w << 6) + cc.w], 1);
        atomicAdd(&h[(pd.x << 6) + cd.x], 1);
        atomicAdd(&h[(pd.y << 6) + cd.y], 1);
        atomicAdd(&h[(pd.z << 6) + cd.z], 1);
        atomicAdd(&h[(pd.w << 6) + cd.w], 1);
    }

    // Scalar tail (n % 16; N = 16777216 divisible, kept for safety).
    for (int i = (n16 << 4) + tid; i < n; i += stride) {
        atomicAdd(&h[(prev[i] << 6) + curr[i]], 1);
    }

    __syncthreads();

    // Flush: one float atomic per non-empty bin per CTA (148 * 4096 total).
    #pragma unroll
    for (int i = threadIdx.x; i < NUM_BINS; i += THREADS) {
        int v = h[i];
        if (v != 0) {
            atomicAdd(&out[i], (float)v);
        }
    }
}

// ---------------------------------------------------------------------------
// Launcher
// ---------------------------------------------------------------------------
extern "C" void kernel_launch(void* const* d_in, const int* in_sizes, int n_in,
                              void* d_out, int out_size)
{
    const int*   prev     = (const int*)  d_in[0];
    const int*   curr     = (const int*)  d_in[1];
    const float* trans_in = (const float*)d_in[2];
    const float* total_in = (const float*)d_in[3];
    float*       out      = (float*)d_out;

    const int n = in_sizes[0];

    // Seed output first; hist flush atomics accumulate onto it.
    tt_init_out<<<(NUM_BINS + 1 + 1023) / 1024, 1024>>>(trans_in, total_in, out,
                                                        out_size, (float)n);

    tt_hist<<<GRID, THREADS>>>(prev, curr, out, n);
}